// round 1
// baseline (speedup 1.0000x reference)
#include <cuda_runtime.h>

// CapsNet dynamic routing, factored so u_hat is never materialized.
//   inp: [256, 1152, 8]  (d_in[0])
//   W:   [1152, 10, 16, 8] (d_in[1])
//   out: v [256, 10, 16]
//
// Per routing iteration t (3 total):
//   c = softmax(b, axis=o)            (fused into Wc build)
//   Wc[ik, ou] = c[i,o] * W[i,o,u,k]
//   s[b, ou]   = inp_flat[b, ik] @ Wc[ik, ou]        (split-K GEMM)
//   v = squash(s)                      (fused with split-K reduce)
//   if t < 2:
//     M[ik, ou] = sum_b inp[b,ik] * v[b,ou]          (GEMM, K=256)
//     b[i,o]   += (1/B) * sum_{k,u} W[i,o,u,k]*M[ik,ou]

#define BATCH   256
#define INCH    1152
#define INU     8
#define OUTCH   10
#define OUTU    16
#define KDIM    (INCH*INU)     // 9216
#define NDIM    (OUTCH*OUTU)   // 160
#define SPLITS  36
#define KC      256            // K per split (36*256 = 9216)

__device__ float g_Wc[KDIM * NDIM];            // 5.9 MB
__device__ float g_part[SPLITS * BATCH * NDIM];// 5.9 MB split-K partials
__device__ float g_v[BATCH * NDIM];
__device__ float g_M[KDIM * NDIM];             // 5.9 MB
__device__ float g_b[INCH * OUTCH];

// ---------------------------------------------------------------------------
// Build Wc[ik, ou] = softmax(b)[i,o] * W[i,o,u,k].  One block per i.
// ---------------------------------------------------------------------------
__global__ void wc_build(const float* __restrict__ W, int t) {
    int i = blockIdx.x;
    float c[OUTCH];
    if (t == 0) {
        #pragma unroll
        for (int o = 0; o < OUTCH; o++) c[o] = 0.1f;
    } else {
        float m = -1e30f;
        #pragma unroll
        for (int o = 0; o < OUTCH; o++) {
            c[o] = g_b[i * OUTCH + o];
            m = fmaxf(m, c[o]);
        }
        float sum = 0.f;
        #pragma unroll
        for (int o = 0; o < OUTCH; o++) { c[o] = expf(c[o] - m); sum += c[o]; }
        float inv = 1.0f / sum;
        #pragma unroll
        for (int o = 0; o < OUTCH; o++) c[o] *= inv;
    }
    const float* Wi = W + (size_t)i * (OUTCH * OUTU * INU); // 1280 per i
    for (int e = threadIdx.x; e < OUTCH * OUTU * INU; e += blockDim.x) {
        int o = e >> 7;            // /128
        int r = e & 127;
        int u = r >> 3;
        int k = r & 7;
        g_Wc[(size_t)(i * INU + k) * NDIM + o * OUTU + u] = Wi[e] * c[o];
    }
}

// ---------------------------------------------------------------------------
// GEMM1 (split-K): g_part[ks][m][n] = sum_{k in split ks} inp[m,k]*Wc[k,n]
// grid (4, 36), 256 threads. Tile: 64(M) x 160(N) x 256(Kc).
// Per-thread register tile 4x10.
// ---------------------------------------------------------------------------
__global__ void __launch_bounds__(256) gemm_s(const float* __restrict__ A) {
    __shared__ float As[8][64];   // [k][m]
    __shared__ float Bs[8][160];  // [k][n]
    int tid = threadIdx.x;
    int m0 = blockIdx.x * 64;
    int k0 = blockIdx.y * KC;
    int tm = tid >> 4;   // 0..15
    int tn = tid & 15;   // 0..15

    float acc[4][10];
    #pragma unroll
    for (int mi = 0; mi < 4; mi++)
        #pragma unroll
        for (int j = 0; j < 10; j++) acc[mi][j] = 0.f;

    for (int kk = 0; kk < KC; kk += 8) {
        // A tile: 64 rows x 8 k (each thread: float2 along k)
        float2 av = *(const float2*)(A + (size_t)(m0 + (tid >> 2)) * KDIM
                                       + k0 + kk + ((tid & 3) << 1));
        As[((tid & 3) << 1) + 0][tid >> 2] = av.x;
        As[((tid & 3) << 1) + 1][tid >> 2] = av.y;
        // B tile: 8 x 160 = 1280 floats, 5 per thread (coalesced along n)
        #pragma unroll
        for (int r = 0; r < 5; r++) {
            int e = tid + 256 * r;
            int br = e / 160, bc = e - br * 160;
            Bs[br][bc] = g_Wc[(size_t)(k0 + kk + br) * NDIM + bc];
        }
        __syncthreads();
        #pragma unroll
        for (int k = 0; k < 8; k++) {
            float4 a = *(const float4*)&As[k][tm << 2];
            float am[4] = {a.x, a.y, a.z, a.w};
            float bb[10];
            #pragma unroll
            for (int j = 0; j < 10; j++) bb[j] = Bs[k][tn + (j << 4)];
            #pragma unroll
            for (int mi = 0; mi < 4; mi++)
                #pragma unroll
                for (int j = 0; j < 10; j++)
                    acc[mi][j] = fmaf(am[mi], bb[j], acc[mi][j]);
        }
        __syncthreads();
    }
    float* P = g_part + (size_t)blockIdx.y * BATCH * NDIM;
    #pragma unroll
    for (int mi = 0; mi < 4; mi++) {
        int m = m0 + (tm << 2) + mi;
        #pragma unroll
        for (int j = 0; j < 10; j++)
            P[(size_t)m * NDIM + tn + (j << 4)] = acc[mi][j];
    }
}

// ---------------------------------------------------------------------------
// GEMM2: g_M[ik, ou] = sum_b inp[b, ik] * g_v[b, ou].
// grid 144, 256 threads. Tile: 64(ik) x 160(ou) x 256(B).
// ---------------------------------------------------------------------------
__global__ void __launch_bounds__(256) gemm_m(const float* __restrict__ A) {
    __shared__ float As[8][64];   // [b][ik]
    __shared__ float Bs[8][160];  // [b][ou]
    int tid = threadIdx.x;
    int m0 = blockIdx.x * 64;
    int tm = tid >> 4;
    int tn = tid & 15;

    float acc[4][10];
    #pragma unroll
    for (int mi = 0; mi < 4; mi++)
        #pragma unroll
        for (int j = 0; j < 10; j++) acc[mi][j] = 0.f;

    for (int kb = 0; kb < BATCH; kb += 8) {
        // A tile: 8 batch rows x 64 ik, coalesced along ik
        float2 av = *(const float2*)(A + (size_t)(kb + (tid >> 5)) * KDIM
                                       + m0 + ((tid & 31) << 1));
        *(float2*)&As[tid >> 5][(tid & 31) << 1] = av;
        // B tile: v rows
        #pragma unroll
        for (int r = 0; r < 5; r++) {
            int e = tid + 256 * r;
            int br = e / 160, bc = e - br * 160;
            Bs[br][bc] = g_v[(size_t)(kb + br) * NDIM + bc];
        }
        __syncthreads();
        #pragma unroll
        for (int k = 0; k < 8; k++) {
            float4 a = *(const float4*)&As[k][tm << 2];
            float am[4] = {a.x, a.y, a.z, a.w};
            float bb[10];
            #pragma unroll
            for (int j = 0; j < 10; j++) bb[j] = Bs[k][tn + (j << 4)];
            #pragma unroll
            for (int mi = 0; mi < 4; mi++)
                #pragma unroll
                for (int j = 0; j < 10; j++)
                    acc[mi][j] = fmaf(am[mi], bb[j], acc[mi][j]);
        }
        __syncthreads();
    }
    #pragma unroll
    for (int mi = 0; mi < 4; mi++) {
        int m = m0 + (tm << 2) + mi;
        #pragma unroll
        for (int j = 0; j < 10; j++)
            g_M[(size_t)m * NDIM + tn + (j << 4)] = acc[mi][j];
    }
}

// ---------------------------------------------------------------------------
// Split-K reduce + squash. One warp per (b,o) row; lanes 0..15 -> u.
// ---------------------------------------------------------------------------
__global__ void squash_k(float* __restrict__ out, int final_iter) {
    int wid = (blockIdx.x * blockDim.x + threadIdx.x) >> 5;
    int lane = threadIdx.x & 31;
    if (wid >= BATCH * OUTCH) return;
    int b = wid / OUTCH, o = wid - b * OUTCH;

    float s = 0.f;
    if (lane < 16) {
        int idx = b * NDIM + o * OUTU + lane;
        #pragma unroll
        for (int sp = 0; sp < SPLITS; sp++)
            s += g_part[(size_t)sp * BATCH * NDIM + idx];
    }
    float sq = s * s;
    // reduce over the 16-lane half (xor 8,4,2,1 stays within halves)
    sq += __shfl_xor_sync(0xffffffffu, sq, 8);
    sq += __shfl_xor_sync(0xffffffffu, sq, 4);
    sq += __shfl_xor_sync(0xffffffffu, sq, 2);
    sq += __shfl_xor_sync(0xffffffffu, sq, 1);

    float scale = sq / ((1.0f + sq) * sqrtf(sq + 1e-9f));
    float* dst = final_iter ? out : g_v;
    if (lane < 16) dst[(size_t)b * NDIM + o * OUTU + lane] = s * scale;
}

// ---------------------------------------------------------------------------
// b update: b[i,o] (+)= (1/B) * sum_{k,u} W[i,o,u,k]*M[i*8+k, o*16+u]
// One warp per (i,o): 128 terms, 4 per lane.
// ---------------------------------------------------------------------------
__global__ void delta_k(const float* __restrict__ W, int t) {
    int gw = (blockIdx.x * blockDim.x + threadIdx.x) >> 5;
    int lane = threadIdx.x & 31;
    if (gw >= INCH * OUTCH) return;
    int i = gw / OUTCH, o = gw - i * OUTCH;

    float sum = 0.f;
    #pragma unroll
    for (int j = 0; j < 4; j++) {
        int e = lane + (j << 5);   // 0..127
        int k = e >> 4;            // 0..7
        int u = e & 15;            // 0..15
        float mv = g_M[(size_t)(i * INU + k) * NDIM + o * OUTU + u];
        float wv = W[(size_t)i * 1280 + (o << 7) + (u << 3) + k];
        sum = fmaf(mv, wv, sum);
    }
    #pragma unroll
    for (int off = 16; off; off >>= 1)
        sum += __shfl_xor_sync(0xffffffffu, sum, off);
    if (lane == 0) {
        float d = sum * (1.0f / (float)BATCH);
        g_b[gw] = (t == 0) ? d : (g_b[gw] + d);
    }
}

// ---------------------------------------------------------------------------
extern "C" void kernel_launch(void* const* d_in, const int* in_sizes, int n_in,
                              void* d_out, int out_size) {
    const float* inp = (const float*)d_in[0];  // [256,1152,8]
    const float* W   = (const float*)d_in[1];  // [1152,10,16,8]
    float* out = (float*)d_out;                // [256,10,16]

    for (int t = 0; t < 3; t++) {
        wc_build<<<INCH, 128>>>(W, t);
        gemm_s<<<dim3(4, SPLITS), 256>>>(inp);
        squash_k<<<(BATCH * OUTCH * 32 + 255) / 256, 256>>>(out, t == 2 ? 1 : 0);
        if (t < 2) {
            gemm_m<<<KDIM / 64, 256>>>(inp);
            delta_k<<<(INCH * OUTCH * 32 + 255) / 256, 256>>>(W, t);
        }
    }
}

// round 4
// speedup vs baseline: 1.8775x; 1.8775x over previous
#include <cuda_runtime.h>
#include <cuda_bf16.h>
#include <cstdint>

// CapsNet dynamic routing. u_hat never materialized; both big contractions are
// bf16 hi/lo 3-pass GEMMs on mma.sync (m16n8k16, fp32 accum).
//   inp: [256, 1152, 8] fp32, W: [1152, 10, 16, 8] fp32, out v: [256, 10, 16] fp32
//
// NOTE: all __device__ globals are referenced ONLY inside device code. Passing
// a __device__ symbol as a host-side kernel argument passes the host shadow
// address, which on GB300 (ATS-coherent) silently reads host zeros.

#define BATCH   256
#define INCH    1152
#define INU     8
#define OUTCH   10
#define OUTU    16
#define KDIM    (INCH*INU)     // 9216
#define NDIM    (OUTCH*OUTU)   // 160
#define SPLITS_S 72            // s-GEMM K splits (128 K per CTA)
#define SPLITS_M 2             // M-GEMM K splits (128 K per CTA)

// ---------------- device globals ----------------
__device__ __nv_bfloat16 g_inp_hi[BATCH * KDIM];
__device__ __nv_bfloat16 g_inp_lo[BATCH * KDIM];
__device__ __nv_bfloat16 g_inpT_hi[KDIM * BATCH];
__device__ __nv_bfloat16 g_inpT_lo[KDIM * BATCH];
__device__ __nv_bfloat16 g_WcT_hi[NDIM * KDIM];
__device__ __nv_bfloat16 g_WcT_lo[NDIM * KDIM];
__device__ __nv_bfloat16 g_vT_hi[NDIM * BATCH];
__device__ __nv_bfloat16 g_vT_lo[NDIM * BATCH];
__device__ float g_part_s[SPLITS_S * BATCH * NDIM];
__device__ float g_part_m[SPLITS_M * KDIM * NDIM];
__device__ float g_b[INCH * OUTCH];

__device__ __forceinline__ uint32_t smem_to_u32(const void* p) {
    uint32_t a;
    asm("{ .reg .u64 t; cvta.to.shared.u64 t, %1; cvt.u32.u64 %0, t; }"
        : "=r"(a) : "l"(p));
    return a;
}

__device__ __forceinline__ void split_bf16(float x, __nv_bfloat16& h, __nv_bfloat16& l) {
    h = __float2bfloat16(x);
    l = __float2bfloat16(x - __bfloat162float(h));
}

// ---------------------------------------------------------------------------
// One-time: inp fp32 -> bf16 hi/lo, plus transposed copies.
// ---------------------------------------------------------------------------
__global__ void conv_inp(const float* __restrict__ inp) {
    __shared__ __nv_bfloat16 sh_hi[32][33];
    __shared__ __nv_bfloat16 sh_lo[32][33];
    int ik0 = blockIdx.x * 32, b0 = blockIdx.y * 32;
    int tx = threadIdx.x, ty = threadIdx.y;
    #pragma unroll
    for (int j = 0; j < 4; j++) {
        int bl = ty + 8 * j;
        float x = inp[(size_t)(b0 + bl) * KDIM + ik0 + tx];
        __nv_bfloat16 h, l;
        split_bf16(x, h, l);
        g_inp_hi[(size_t)(b0 + bl) * KDIM + ik0 + tx] = h;
        g_inp_lo[(size_t)(b0 + bl) * KDIM + ik0 + tx] = l;
        sh_hi[tx][bl] = h;
        sh_lo[tx][bl] = l;
    }
    __syncthreads();
    #pragma unroll
    for (int j = 0; j < 4; j++) {
        int ikl = ty + 8 * j;
        g_inpT_hi[(size_t)(ik0 + ikl) * BATCH + b0 + tx] = sh_hi[ikl][tx];
        g_inpT_lo[(size_t)(ik0 + ikl) * BATCH + b0 + tx] = sh_lo[ikl][tx];
    }
}

// ---------------------------------------------------------------------------
// WcT[ou, i*8+k] = softmax(b)[i,o] * W[i,o,u,k] as bf16 hi/lo.
// One block per i, 160 threads (one per ou).
// ---------------------------------------------------------------------------
__global__ void wc_build(const float* __restrict__ W, int t) {
    int i = blockIdx.x;
    int e = threadIdx.x;             // o*16+u
    int o = e >> 4, u = e & 15;
    float cv;
    if (t == 0) {
        cv = 0.1f;
    } else {
        float bv[OUTCH], m = -1e30f;
        #pragma unroll
        for (int oo = 0; oo < OUTCH; oo++) {
            bv[oo] = g_b[i * OUTCH + oo];
            m = fmaxf(m, bv[oo]);
        }
        float sum = 0.f;
        #pragma unroll
        for (int oo = 0; oo < OUTCH; oo++) { bv[oo] = expf(bv[oo] - m); sum += bv[oo]; }
        cv = bv[o] / sum;
    }
    const float* src = W + (size_t)i * 1280 + (o << 7) + (u << 3);
    __nv_bfloat16 th[8], tl[8];
    #pragma unroll
    for (int k = 0; k < 8; k++) split_bf16(src[k] * cv, th[k], tl[k]);
    uint4 ph, pl;
    uint32_t* wh = (uint32_t*)&ph;
    uint32_t* wl = (uint32_t*)&pl;
    #pragma unroll
    for (int w = 0; w < 4; w++) {
        wh[w] = (uint32_t)__bfloat16_as_ushort(th[2*w]) |
                ((uint32_t)__bfloat16_as_ushort(th[2*w+1]) << 16);
        wl[w] = (uint32_t)__bfloat16_as_ushort(tl[2*w]) |
                ((uint32_t)__bfloat16_as_ushort(tl[2*w+1]) << 16);
    }
    *(uint4*)(g_WcT_hi + (size_t)e * KDIM + i * 8) = ph;
    *(uint4*)(g_WcT_lo + (size_t)e * KDIM + i * 8) = pl;
}

// ---------------------------------------------------------------------------
// mma.sync warp-tiled GEMM. D[128,160] fp32 = 3-pass hi/lo accumulation of
//   A[m0..m0+127, k0..k0+127] @ B[0..159, k0..k0+127]^T  (A [m][k], B [n][k])
// grid (Mtiles, Ksplits), 256 threads, 8 warps (4M x 2N).
// which==0: s-GEMM  (A=g_inp,  B=g_WcT, lda=ldb=KDIM,  part=g_part_s)
// which==1: M-GEMM  (A=g_inpT, B=g_vT,  lda=ldb=BATCH, part=g_part_m)
// Operand arrays resolved INSIDE device code (see note at top).
// ---------------------------------------------------------------------------
#define KCHUNK 64
#define APITCH 72   // smem row pitch in bf16 (144 B: 16B-aligned rows)

__device__ __forceinline__ void ldsm4(uint32_t& r0, uint32_t& r1, uint32_t& r2,
                                      uint32_t& r3, uint32_t addr) {
    asm volatile("ldmatrix.sync.aligned.m8n8.x4.shared.b16 {%0,%1,%2,%3}, [%4];"
                 : "=r"(r0), "=r"(r1), "=r"(r2), "=r"(r3) : "r"(addr));
}
__device__ __forceinline__ void mma16816(float* d, const uint32_t* a,
                                         const uint32_t* b) {
    asm volatile(
        "mma.sync.aligned.m16n8k16.row.col.f32.bf16.bf16.f32 "
        "{%0,%1,%2,%3}, {%4,%5,%6,%7}, {%8,%9}, {%0,%1,%2,%3};"
        : "+f"(d[0]), "+f"(d[1]), "+f"(d[2]), "+f"(d[3])
        : "r"(a[0]), "r"(a[1]), "r"(a[2]), "r"(a[3]), "r"(b[0]), "r"(b[1]));
}

__global__ void __launch_bounds__(256, 1)
gemm_mma(int which, int kcta) {
    const __nv_bfloat16* A_hi = (which == 0) ? g_inp_hi : g_inpT_hi;
    const __nv_bfloat16* A_lo = (which == 0) ? g_inp_lo : g_inpT_lo;
    const __nv_bfloat16* B_hi = (which == 0) ? g_WcT_hi : g_vT_hi;
    const __nv_bfloat16* B_lo = (which == 0) ? g_WcT_lo : g_vT_lo;
    float* part = (which == 0) ? g_part_s : g_part_m;
    const int lda = (which == 0) ? KDIM : BATCH;
    const int ldb = lda;

    __shared__ __nv_bfloat16 As[128 * APITCH];
    __shared__ __nv_bfloat16 Bs[160 * APITCH];

    int tid = threadIdx.x, lane = tid & 31, wid = tid >> 5;
    int warp_m = wid & 3, warp_n = wid >> 2;       // 4 x 2 warp grid
    int m0 = blockIdx.x * 128;
    int k0 = blockIdx.y * kcta;
    int nch = kcta / KCHUNK;                        // chunks per pass (2)
    int total = 3 * nch;

    float acc[2][10][4];
    #pragma unroll
    for (int mi = 0; mi < 2; mi++)
        #pragma unroll
        for (int nt = 0; nt < 10; nt++)
            #pragma unroll
            for (int r = 0; r < 4; r++) acc[mi][nt][r] = 0.f;

    uint32_t sA = smem_to_u32(As), sB = smem_to_u32(Bs);

    // ldmatrix lane address components
    int a_row_l = ((lane >> 3) & 1) * 8 + (lane & 7);
    int a_k_l   = (lane >> 4) * 8;
    int b_dn_l  = ((lane >> 4) & 1) * 8 + (lane & 7);
    int b_dk_l  = ((lane >> 3) & 1) * 8;

    uint4 pa[4], pb[5];
    auto preload = [&](int g) {
        int p = g / nch, c = g % nch;
        const __nv_bfloat16* Asrc = (p == 2) ? A_lo : A_hi;
        const __nv_bfloat16* Bsrc = (p == 1) ? B_lo : B_hi;
        int kb = k0 + c * KCHUNK;
        #pragma unroll
        for (int r = 0; r < 4; r++) {
            int e = tid + (r << 8);
            int row = e >> 3, j = e & 7;
            pa[r] = *(const uint4*)(Asrc + (size_t)(m0 + row) * lda + kb + (j << 3));
        }
        #pragma unroll
        for (int r = 0; r < 5; r++) {
            int e = tid + (r << 8);
            int row = e >> 3, j = e & 7;
            pb[r] = *(const uint4*)(Bsrc + (size_t)row * ldb + kb + (j << 3));
        }
    };

    preload(0);
    for (int g = 0; g < total; g++) {
        #pragma unroll
        for (int r = 0; r < 4; r++) {
            int e = tid + (r << 8);
            int row = e >> 3, j = e & 7;
            *(uint4*)(As + row * APITCH + (j << 3)) = pa[r];
        }
        #pragma unroll
        for (int r = 0; r < 5; r++) {
            int e = tid + (r << 8);
            int row = e >> 3, j = e & 7;
            *(uint4*)(Bs + row * APITCH + (j << 3)) = pb[r];
        }
        __syncthreads();
        if (g + 1 < total) preload(g + 1);

        #pragma unroll
        for (int ks = 0; ks < KCHUNK / 16; ks++) {
            uint32_t af[2][4], bf[10][2];
            #pragma unroll
            for (int mi = 0; mi < 2; mi++) {
                int row = warp_m * 32 + mi * 16 + a_row_l;
                uint32_t addr = sA + (uint32_t)(row * APITCH + ks * 16 + a_k_l) * 2;
                ldsm4(af[mi][0], af[mi][1], af[mi][2], af[mi][3], addr);
            }
            #pragma unroll
            for (int p = 0; p < 5; p++) {
                int row = warp_n * 80 + p * 16 + b_dn_l;
                uint32_t addr = sB + (uint32_t)(row * APITCH + ks * 16 + b_dk_l) * 2;
                ldsm4(bf[2*p][0], bf[2*p][1], bf[2*p+1][0], bf[2*p+1][1], addr);
            }
            #pragma unroll
            for (int mi = 0; mi < 2; mi++)
                #pragma unroll
                for (int nt = 0; nt < 10; nt++)
                    mma16816(acc[mi][nt], af[mi], bf[nt]);
        }
        __syncthreads();
    }

    // Epilogue: D fragment -> partials [128][160] row-major per CTA tile.
    float* out = part + ((size_t)blockIdx.y * gridDim.x + blockIdx.x) * 128 * NDIM;
    int r_l = lane >> 2, c_l = (lane & 3) * 2;
    #pragma unroll
    for (int mi = 0; mi < 2; mi++) {
        int row = warp_m * 32 + mi * 16 + r_l;
        #pragma unroll
        for (int nt = 0; nt < 10; nt++) {
            int col = warp_n * 80 + nt * 8 + c_l;
            *(float2*)(out + (size_t)row * NDIM + col) =
                make_float2(acc[mi][nt][0], acc[mi][nt][1]);
            *(float2*)(out + (size_t)(row + 8) * NDIM + col) =
                make_float2(acc[mi][nt][2], acc[mi][nt][3]);
        }
    }
}

// ---------------------------------------------------------------------------
// Split-K reduce + squash. One warp per (b,o); lanes 0..15 -> u.
// ---------------------------------------------------------------------------
__global__ void squash_k(float* __restrict__ out, int t) {
    int wid = (blockIdx.x * blockDim.x + threadIdx.x) >> 5;
    int lane = threadIdx.x & 31;
    if (wid >= BATCH * OUTCH) return;
    int b = wid / OUTCH, o = wid - b * OUTCH;

    float s = 0.f;
    if (lane < 16) {
        int idx = b * NDIM + o * OUTU + lane;
        #pragma unroll 8
        for (int sp = 0; sp < SPLITS_S; sp++)
            s += g_part_s[(size_t)sp * BATCH * NDIM + idx];
    }
    float sq = s * s;
    sq += __shfl_xor_sync(0xffffffffu, sq, 8);
    sq += __shfl_xor_sync(0xffffffffu, sq, 4);
    sq += __shfl_xor_sync(0xffffffffu, sq, 2);
    sq += __shfl_xor_sync(0xffffffffu, sq, 1);
    float scale = sq / ((1.0f + sq) * sqrtf(sq + 1e-9f));
    float v = s * scale;
    if (lane < 16) {
        if (t == 2) {
            out[(size_t)b * NDIM + o * OUTU + lane] = v;
        } else {
            __nv_bfloat16 h, l;
            split_bf16(v, h, l);
            g_vT_hi[(size_t)(o * OUTU + lane) * BATCH + b] = h;
            g_vT_lo[(size_t)(o * OUTU + lane) * BATCH + b] = l;
        }
    }
}

// ---------------------------------------------------------------------------
// b[i,o] (+)= (1/B) sum_{k,u} W[i,o,u,k] * M[i*8+k, o*16+u],
// M = part_m[0] + part_m[1]. One warp per (i,o).
// ---------------------------------------------------------------------------
__global__ void delta_k(const float* __restrict__ W, int t) {
    int gw = (blockIdx.x * blockDim.x + threadIdx.x) >> 5;
    int lane = threadIdx.x & 31;
    if (gw >= INCH * OUTCH) return;
    int i = gw / OUTCH, o = gw - i * OUTCH;

    float sum = 0.f;
    #pragma unroll
    for (int j = 0; j < 4; j++) {
        int e = lane + (j << 5);
        int k = e >> 4;
        int u = e & 15;
        size_t idx = (size_t)(i * INU + k) * NDIM + o * OUTU + u;
        float mv = g_part_m[idx] + g_part_m[(size_t)KDIM * NDIM + idx];
        float wv = W[(size_t)i * 1280 + (o << 7) + (u << 3) + k];
        sum = fmaf(mv, wv, sum);
    }
    #pragma unroll
    for (int off = 16; off; off >>= 1)
        sum += __shfl_xor_sync(0xffffffffu, sum, off);
    if (lane == 0) {
        float d = sum * (1.0f / (float)BATCH);
        g_b[gw] = (t == 0) ? d : (g_b[gw] + d);
    }
}

// ---------------------------------------------------------------------------
extern "C" void kernel_launch(void* const* d_in, const int* in_sizes, int n_in,
                              void* d_out, int out_size) {
    const float* inp = (const float*)d_in[0];  // [256,1152,8]
    const float* W   = (const float*)d_in[1];  // [1152,10,16,8]
    float* out = (float*)d_out;                // [256,10,16]

    conv_inp<<<dim3(KDIM / 32, BATCH / 32), dim3(32, 8)>>>(inp);

    for (int t = 0; t < 3; t++) {
        wc_build<<<INCH, NDIM>>>(W, t);
        gemm_mma<<<dim3(2, SPLITS_S), 256>>>(0, KDIM / SPLITS_S);
        squash_k<<<(BATCH * OUTCH * 32 + 255) / 256, 256>>>(out, t);
        if (t < 2) {
            gemm_mma<<<dim3(KDIM / 128, SPLITS_M), 256>>>(1, BATCH / SPLITS_M);
            delta_k<<<(INCH * OUTCH * 32 + 255) / 256, 256>>>(W, t);
        }
    }
}

// round 5
// speedup vs baseline: 1.9509x; 1.0391x over previous
#include <cuda_runtime.h>
#include <cuda_bf16.h>
#include <cstdint>

// CapsNet dynamic routing. u_hat never materialized; bf16 hi/lo 3-pass GEMMs
// on mma.sync (m16n8k16, fp32 accum). Wc construction fused into the s-GEMM;
// the b-update contraction fused into the M-GEMM epilogue.
//   inp: [256,1152,8] fp32, W: [1152,10,16,8] fp32, out v: [256,10,16] fp32
//
// All __device__ globals referenced only inside device code (host-passed
// __device__ symbols silently resolve to ATS host memory on GB300).

#define BATCH   256
#define INCH    1152
#define INU     8
#define OUTCH   10
#define OUTU    16
#define KDIM    (INCH*INU)     // 9216
#define NDIM    (OUTCH*OUTU)   // 160
#define SPLITS_S 72            // s-GEMM K splits (128 K = 16 capsules per CTA)

// ---------------- device globals ----------------
__device__ __nv_bfloat16 g_inp_hi[BATCH * KDIM];
__device__ __nv_bfloat16 g_inp_lo[BATCH * KDIM];
__device__ __nv_bfloat16 g_inpT_hi[KDIM * BATCH];
__device__ __nv_bfloat16 g_inpT_lo[KDIM * BATCH];
__device__ __nv_bfloat16 g_vT_hi[NDIM * BATCH];
__device__ __nv_bfloat16 g_vT_lo[NDIM * BATCH];
__device__ float g_part_s[SPLITS_S * BATCH * NDIM];   // 11.8 MB
__device__ float g_b[INCH * OUTCH];

__device__ __forceinline__ uint32_t smem_to_u32(const void* p) {
    uint32_t a;
    asm("{ .reg .u64 t; cvta.to.shared.u64 t, %1; cvt.u32.u64 %0, t; }"
        : "=r"(a) : "l"(p));
    return a;
}
__device__ __forceinline__ void split_bf16(float x, __nv_bfloat16& h, __nv_bfloat16& l) {
    h = __float2bfloat16(x);
    l = __float2bfloat16(x - __bfloat162float(h));
}
__device__ __forceinline__ void ldsm4(uint32_t& r0, uint32_t& r1, uint32_t& r2,
                                      uint32_t& r3, uint32_t addr) {
    asm volatile("ldmatrix.sync.aligned.m8n8.x4.shared.b16 {%0,%1,%2,%3}, [%4];"
                 : "=r"(r0), "=r"(r1), "=r"(r2), "=r"(r3) : "r"(addr));
}
__device__ __forceinline__ void mma16816(float* d, const uint32_t* a,
                                         const uint32_t* b) {
    asm volatile(
        "mma.sync.aligned.m16n8k16.row.col.f32.bf16.bf16.f32 "
        "{%0,%1,%2,%3}, {%4,%5,%6,%7}, {%8,%9}, {%0,%1,%2,%3};"
        : "+f"(d[0]), "+f"(d[1]), "+f"(d[2]), "+f"(d[3])
        : "r"(a[0]), "r"(a[1]), "r"(a[2]), "r"(a[3]), "r"(b[0]), "r"(b[1]));
}

// ---------------------------------------------------------------------------
// One-time: inp fp32 -> bf16 hi/lo, plus transposed copies.
// ---------------------------------------------------------------------------
__global__ void conv_inp(const float* __restrict__ inp) {
    __shared__ __nv_bfloat16 sh_hi[32][33];
    __shared__ __nv_bfloat16 sh_lo[32][33];
    int ik0 = blockIdx.x * 32, b0 = blockIdx.y * 32;
    int tx = threadIdx.x, ty = threadIdx.y;
    #pragma unroll
    for (int j = 0; j < 4; j++) {
        int bl = ty + 8 * j;
        float x = inp[(size_t)(b0 + bl) * KDIM + ik0 + tx];
        __nv_bfloat16 h, l;
        split_bf16(x, h, l);
        g_inp_hi[(size_t)(b0 + bl) * KDIM + ik0 + tx] = h;
        g_inp_lo[(size_t)(b0 + bl) * KDIM + ik0 + tx] = l;
        sh_hi[tx][bl] = h;
        sh_lo[tx][bl] = l;
    }
    __syncthreads();
    #pragma unroll
    for (int j = 0; j < 4; j++) {
        int ikl = ty + 8 * j;
        g_inpT_hi[(size_t)(ik0 + ikl) * BATCH + b0 + tx] = sh_hi[ikl][tx];
        g_inpT_lo[(size_t)(ik0 + ikl) * BATCH + b0 + tx] = sh_lo[ikl][tx];
    }
}

// ---------------------------------------------------------------------------
// s-GEMM with fused Wc construction.
// grid (2 Mtiles, 72 Ksplits), 256 threads, 8 warps (4M x 2N).
// CTA handles A[m0..m0+128, 128 k] x Wc^T for capsules i0..i0+16.
// Dynamic smem 64KB: c_s | Bh(160x72) | Bl | As(128x72).
// ---------------------------------------------------------------------------
#define PITCH 72   // bf16 row pitch (144 B; 16B-aligned, ldmatrix conflict-free)
#define SMS_CS  0
#define SMS_BH  1024
#define SMS_BL  (1024 + 160*PITCH*2)          // 24064
#define SMS_AS  (SMS_BL + 160*PITCH*2)        // 47104
#define SMS_TOT (SMS_AS + 128*PITCH*2)        // 65536

__global__ void __launch_bounds__(256, 1)
gemm_s_fused(const float* __restrict__ W, int t) {
    extern __shared__ char sm[];
    float* c_s = (float*)(sm + SMS_CS);
    __nv_bfloat16* Bh = (__nv_bfloat16*)(sm + SMS_BH);
    __nv_bfloat16* Bl = (__nv_bfloat16*)(sm + SMS_BL);
    __nv_bfloat16* As = (__nv_bfloat16*)(sm + SMS_AS);

    int tid = threadIdx.x, lane = tid & 31, wid = tid >> 5;
    int warp_m = wid & 3, warp_n = wid >> 2;
    int m0 = blockIdx.x * 128;
    int i0 = blockIdx.y * 16;           // capsules for this CTA

    // softmax coefficients for the 16 capsules
    if (tid < 16) {
        int i = i0 + tid;
        if (t == 0) {
            #pragma unroll
            for (int o = 0; o < OUTCH; o++) c_s[tid * 10 + o] = 0.1f;
        } else {
            float bv[OUTCH], m = -1e30f;
            #pragma unroll
            for (int o = 0; o < OUTCH; o++) {
                bv[o] = g_b[i * OUTCH + o];
                m = fmaxf(m, bv[o]);
            }
            float sum = 0.f;
            #pragma unroll
            for (int o = 0; o < OUTCH; o++) { bv[o] = expf(bv[o] - m); sum += bv[o]; }
            float inv = 1.0f / sum;
            #pragma unroll
            for (int o = 0; o < OUTCH; o++) c_s[tid * 10 + o] = bv[o] * inv;
        }
    }
    __syncthreads();

    float acc[2][10][4];
    #pragma unroll
    for (int mi = 0; mi < 2; mi++)
        #pragma unroll
        for (int nt = 0; nt < 10; nt++)
            #pragma unroll
            for (int r = 0; r < 4; r++) acc[mi][nt][r] = 0.f;

    uint32_t sA = smem_to_u32(As);
    uint32_t sBh = smem_to_u32(Bh), sBl = smem_to_u32(Bl);

    int a_row_l = ((lane >> 3) & 1) * 8 + (lane & 7);
    int a_k_l   = (lane >> 4) * 8;
    int b_dn_l  = ((lane >> 4) & 1) * 8 + (lane & 7);
    int b_dk_l  = ((lane >> 3) & 1) * 8;

    auto do_pass = [&](uint32_t sBp) {
        #pragma unroll
        for (int ks = 0; ks < 4; ks++) {
            uint32_t af[2][4], bf[10][2];
            #pragma unroll
            for (int mi = 0; mi < 2; mi++) {
                int row = warp_m * 32 + mi * 16 + a_row_l;
                ldsm4(af[mi][0], af[mi][1], af[mi][2], af[mi][3],
                      sA + (uint32_t)(row * PITCH + ks * 16 + a_k_l) * 2);
            }
            #pragma unroll
            for (int p = 0; p < 5; p++) {
                int row = warp_n * 80 + p * 16 + b_dn_l;
                ldsm4(bf[2*p][0], bf[2*p][1], bf[2*p+1][0], bf[2*p+1][1],
                      sBp + (uint32_t)(row * PITCH + ks * 16 + b_dk_l) * 2);
            }
            #pragma unroll
            for (int mi = 0; mi < 2; mi++)
                #pragma unroll
                for (int nt = 0; nt < 10; nt++)
                    mma16816(acc[mi][nt], af[mi], bf[nt]);
        }
    };

    for (int ch = 0; ch < 2; ch++) {
        // Build B chunk (8 capsules -> 160 x 64) from W, scaled, hi/lo.
        const float4* W4 = (const float4*)(W + (size_t)(i0 + ch * 8) * 1280);
        #pragma unroll
        for (int r = 0; r < 10; r++) {
            int q = tid + (r << 8);              // 0..2559 float4s
            int i_off = q / 320;
            int rem = q - i_off * 320;           // within one capsule (320 f4)
            int o = rem >> 5;                    // /32
            int rem2 = rem & 31;
            int u = rem2 >> 1, kh = rem2 & 1;
            float4 f = W4[q];
            float cv = c_s[(ch * 8 + i_off) * 10 + o];
            __nv_bfloat16 h0,l0,h1,l1,h2,l2,h3,l3;
            split_bf16(f.x * cv, h0, l0);
            split_bf16(f.y * cv, h1, l1);
            split_bf16(f.z * cv, h2, l2);
            split_bf16(f.w * cv, h3, l3);
            uint2 ph, pl;
            ph.x = (uint32_t)__bfloat16_as_ushort(h0) | ((uint32_t)__bfloat16_as_ushort(h1) << 16);
            ph.y = (uint32_t)__bfloat16_as_ushort(h2) | ((uint32_t)__bfloat16_as_ushort(h3) << 16);
            pl.x = (uint32_t)__bfloat16_as_ushort(l0) | ((uint32_t)__bfloat16_as_ushort(l1) << 16);
            pl.y = (uint32_t)__bfloat16_as_ushort(l2) | ((uint32_t)__bfloat16_as_ushort(l3) << 16);
            int off = (o * 16 + u) * PITCH + i_off * 8 + kh * 4;
            *(uint2*)(Bh + off) = ph;
            *(uint2*)(Bl + off) = pl;
        }
        // Load A hi chunk (128 x 64)
        int kb = blockIdx.y * 128 + ch * 64;
        #pragma unroll
        for (int r = 0; r < 4; r++) {
            int e = tid + (r << 8);
            int row = e >> 3, j = e & 7;
            *(uint4*)(As + row * PITCH + (j << 3)) =
                *(const uint4*)(g_inp_hi + (size_t)(m0 + row) * KDIM + kb + (j << 3));
        }
        __syncthreads();
        do_pass(sBh);               // Ah x Bh
        do_pass(sBl);               // Ah x Bl
        __syncthreads();
        // Load A lo chunk into the same buffer
        #pragma unroll
        for (int r = 0; r < 4; r++) {
            int e = tid + (r << 8);
            int row = e >> 3, j = e & 7;
            *(uint4*)(As + row * PITCH + (j << 3)) =
                *(const uint4*)(g_inp_lo + (size_t)(m0 + row) * KDIM + kb + (j << 3));
        }
        __syncthreads();
        do_pass(sBh);               // Al x Bh
        __syncthreads();
    }

    // Epilogue: partial tile -> g_part_s[(by*2+bx)][128][160]
    float* out = g_part_s + ((size_t)blockIdx.y * 2 + blockIdx.x) * 128 * NDIM;
    int r_l = lane >> 2, c_l = (lane & 3) * 2;
    #pragma unroll
    for (int mi = 0; mi < 2; mi++) {
        int row = warp_m * 32 + mi * 16 + r_l;
        #pragma unroll
        for (int nt = 0; nt < 10; nt++) {
            int col = warp_n * 80 + nt * 8 + c_l;
            *(float2*)(out + (size_t)row * NDIM + col) =
                make_float2(acc[mi][nt][0], acc[mi][nt][1]);
            *(float2*)(out + (size_t)(row + 8) * NDIM + col) =
                make_float2(acc[mi][nt][2], acc[mi][nt][3]);
        }
    }
}

// ---------------------------------------------------------------------------
// Split-K reduce + squash, one thread per output element (40960 threads).
// Half-warp shuffle computes the 16-wide squared norm.
// ---------------------------------------------------------------------------
__global__ void squash_k(float* __restrict__ out, int t) {
    int idx = blockIdx.x * 256 + threadIdx.x;    // b*160 + o*16 + u
    float a0 = 0.f, a1 = 0.f, a2 = 0.f, a3 = 0.f;
    #pragma unroll
    for (int sp = 0; sp < SPLITS_S; sp += 4) {
        a0 += g_part_s[(size_t)(sp + 0) * (BATCH * NDIM) + idx];
        a1 += g_part_s[(size_t)(sp + 1) * (BATCH * NDIM) + idx];
        a2 += g_part_s[(size_t)(sp + 2) * (BATCH * NDIM) + idx];
        a3 += g_part_s[(size_t)(sp + 3) * (BATCH * NDIM) + idx];
    }
    float s = (a0 + a1) + (a2 + a3);
    float sq = s * s;
    sq += __shfl_xor_sync(0xffffffffu, sq, 8);
    sq += __shfl_xor_sync(0xffffffffu, sq, 4);
    sq += __shfl_xor_sync(0xffffffffu, sq, 2);
    sq += __shfl_xor_sync(0xffffffffu, sq, 1);
    float scale = sq / ((1.0f + sq) * sqrtf(sq + 1e-9f));
    float v = s * scale;
    if (t == 2) {
        out[idx] = v;
    } else {
        int b = idx / NDIM;
        int ou = idx - b * NDIM;
        __nv_bfloat16 h, l;
        split_bf16(v, h, l);
        g_vT_hi[(size_t)ou * BATCH + b] = h;
        g_vT_lo[(size_t)ou * BATCH + b] = l;
    }
}

// ---------------------------------------------------------------------------
// M-GEMM (M[ik,ou] = inpT @ vT^T) with fused b-update epilogue.
// grid 72 CTAs (128 ik rows each = 16 capsules), K = 256 (batch), no split.
// Dynamic smem 80KB: mainloop As|Bs (41KB), epilogue M_s (80KB, reused).
// ---------------------------------------------------------------------------
#define SMM_AS 0
#define SMM_BS (128*PITCH*2)        // 18432
#define SMM_TOT (128*NDIM*4)        // 81920 (epilogue M tile)

__global__ void __launch_bounds__(256, 1)
gemm_m_fused(const float* __restrict__ W, int t) {
    extern __shared__ char sm[];
    __nv_bfloat16* As = (__nv_bfloat16*)(sm + SMM_AS);
    __nv_bfloat16* Bs = (__nv_bfloat16*)(sm + SMM_BS);

    int tid = threadIdx.x, lane = tid & 31, wid = tid >> 5;
    int warp_m = wid & 3, warp_n = wid >> 2;
    int m0 = blockIdx.x * 128;

    float acc[2][10][4];
    #pragma unroll
    for (int mi = 0; mi < 2; mi++)
        #pragma unroll
        for (int nt = 0; nt < 10; nt++)
            #pragma unroll
            for (int r = 0; r < 4; r++) acc[mi][nt][r] = 0.f;

    uint32_t sA = smem_to_u32(As), sB = smem_to_u32(Bs);
    int a_row_l = ((lane >> 3) & 1) * 8 + (lane & 7);
    int a_k_l   = (lane >> 4) * 8;
    int b_dn_l  = ((lane >> 4) & 1) * 8 + (lane & 7);
    int b_dk_l  = ((lane >> 3) & 1) * 8;

    uint4 pa[4], pb[5];
    auto preload = [&](int g) {
        int p = g >> 2, c = g & 3;               // 3 passes x 4 chunks of 64
        const __nv_bfloat16* Asrc = (p == 2) ? g_inpT_lo : g_inpT_hi;
        const __nv_bfloat16* Bsrc = (p == 1) ? g_vT_lo : g_vT_hi;
        int kb = c << 6;
        #pragma unroll
        for (int r = 0; r < 4; r++) {
            int e = tid + (r << 8);
            int row = e >> 3, j = e & 7;
            pa[r] = *(const uint4*)(Asrc + (size_t)(m0 + row) * BATCH + kb + (j << 3));
        }
        #pragma unroll
        for (int r = 0; r < 5; r++) {
            int e = tid + (r << 8);
            int row = e >> 3, j = e & 7;
            pb[r] = *(const uint4*)(Bsrc + (size_t)row * BATCH + kb + (j << 3));
        }
    };

    preload(0);
    for (int g = 0; g < 12; g++) {
        #pragma unroll
        for (int r = 0; r < 4; r++) {
            int e = tid + (r << 8);
            int row = e >> 3, j = e & 7;
            *(uint4*)(As + row * PITCH + (j << 3)) = pa[r];
        }
        #pragma unroll
        for (int r = 0; r < 5; r++) {
            int e = tid + (r << 8);
            int row = e >> 3, j = e & 7;
            *(uint4*)(Bs + row * PITCH + (j << 3)) = pb[r];
        }
        __syncthreads();
        if (g + 1 < 12) preload(g + 1);

        #pragma unroll
        for (int ks = 0; ks < 4; ks++) {
            uint32_t af[2][4], bf[10][2];
            #pragma unroll
            for (int mi = 0; mi < 2; mi++) {
                int row = warp_m * 32 + mi * 16 + a_row_l;
                ldsm4(af[mi][0], af[mi][1], af[mi][2], af[mi][3],
                      sA + (uint32_t)(row * PITCH + ks * 16 + a_k_l) * 2);
            }
            #pragma unroll
            for (int p = 0; p < 5; p++) {
                int row = warp_n * 80 + p * 16 + b_dn_l;
                ldsm4(bf[2*p][0], bf[2*p][1], bf[2*p+1][0], bf[2*p+1][1],
                      sB + (uint32_t)(row * PITCH + ks * 16 + b_dk_l) * 2);
            }
            #pragma unroll
            for (int mi = 0; mi < 2; mi++)
                #pragma unroll
                for (int nt = 0; nt < 10; nt++)
                    mma16816(acc[mi][nt], af[mi], bf[nt]);
        }
        __syncthreads();
    }

    // Stage M tile [128][160] fp32 in smem (reuses As/Bs space).
    float* M_s = (float*)sm;
    int r_l = lane >> 2, c_l = (lane & 3) * 2;
    #pragma unroll
    for (int mi = 0; mi < 2; mi++) {
        int row = warp_m * 32 + mi * 16 + r_l;
        #pragma unroll
        for (int nt = 0; nt < 10; nt++) {
            int col = warp_n * 80 + nt * 8 + c_l;
            *(float2*)(M_s + row * NDIM + col) =
                make_float2(acc[mi][nt][0], acc[mi][nt][1]);
            *(float2*)(M_s + (row + 8) * NDIM + col) =
                make_float2(acc[mi][nt][2], acc[mi][nt][3]);
        }
    }
    __syncthreads();

    // Fused b-update: delta[i,o] = (1/B) sum_{k,u} W[i,o,u,k] * M[i8+k][o16+u]
    // 160 outputs per CTA (16 capsules x 10), 20 per warp.
    #pragma unroll
    for (int ee = 0; ee < 20; ee++) {
        int e = wid * 20 + ee;
        int i_rel = e / 10, o = e - i_rel * 10;
        int i = blockIdx.x * 16 + i_rel;
        float sum = 0.f;
        #pragma unroll
        for (int j = 0; j < 4; j++) {
            int f = lane + (j << 5);           // 0..127
            int k = f >> 4, u = f & 15;
            sum = fmaf(W[(size_t)i * 1280 + (o << 7) + (u << 3) + k],
                       M_s[(i_rel * 8 + k) * NDIM + o * 16 + u], sum);
        }
        #pragma unroll
        for (int off = 16; off; off >>= 1)
            sum += __shfl_xor_sync(0xffffffffu, sum, off);
        if (lane == 0) {
            float d = sum * (1.0f / (float)BATCH);
            int gw = i * OUTCH + o;
            g_b[gw] = (t == 0) ? d : (g_b[gw] + d);
        }
    }
}

// ---------------------------------------------------------------------------
extern "C" void kernel_launch(void* const* d_in, const int* in_sizes, int n_in,
                              void* d_out, int out_size) {
    const float* inp = (const float*)d_in[0];  // [256,1152,8]
    const float* W   = (const float*)d_in[1];  // [1152,10,16,8]
    float* out = (float*)d_out;                // [256,10,16]

    cudaFuncSetAttribute(gemm_s_fused,
                         cudaFuncAttributeMaxDynamicSharedMemorySize, SMS_TOT);
    cudaFuncSetAttribute(gemm_m_fused,
                         cudaFuncAttributeMaxDynamicSharedMemorySize, SMM_TOT);

    conv_inp<<<dim3(KDIM / 32, BATCH / 32), dim3(32, 8)>>>(inp);

    for (int t = 0; t < 3; t++) {
        gemm_s_fused<<<dim3(2, SPLITS_S), 256, SMS_TOT>>>(W, t);
        squash_k<<<BATCH * NDIM / 256, 256>>>(out, t);
        if (t < 2)
            gemm_m_fused<<<KDIM / 128, 256, SMM_TOT>>>(W, t);
    }
}

// round 6
// speedup vs baseline: 2.1283x; 1.0909x over previous
#include <cuda_runtime.h>
#include <cuda_bf16.h>
#include <cstdint>

// CapsNet dynamic routing. u_hat never materialized; bf16 hi/lo 3-pass GEMMs
// on mma.sync (m16n8k16, fp32 accum).
//   inp: [256,1152,8] fp32, W: [1152,10,16,8] fp32, out v: [256,10,16] fp32
//
// All __device__ globals referenced only inside device code (host-passed
// __device__ symbols silently resolve to ATS host memory on GB300).

#define BATCH   256
#define INCH    1152
#define INU     8
#define OUTCH   10
#define OUTU    16
#define KDIM    (INCH*INU)     // 9216
#define NDIM    (OUTCH*OUTU)   // 160
#define NCHUNK  144            // 64-k chunks (8 capsules each)
#define SPLITS_S 72            // s-GEMM K splits (2 chunks per CTA)

// ---------------- device globals ----------------
__device__ __nv_bfloat16 g_inp_hi[BATCH * KDIM];
__device__ __nv_bfloat16 g_inp_lo[BATCH * KDIM];
__device__ __nv_bfloat16 g_inpT_hi[KDIM * BATCH];
__device__ __nv_bfloat16 g_inpT_lo[KDIM * BATCH];
__device__ __nv_bfloat16 g_vT_hi[NDIM * BATCH];
__device__ __nv_bfloat16 g_vT_lo[NDIM * BATCH];
__device__ __nv_bfloat16 g_Bt_hi[NCHUNK * NDIM * 64];  // chunk-tiled Wc
__device__ __nv_bfloat16 g_Bt_lo[NCHUNK * NDIM * 64];
__device__ float g_part_s[SPLITS_S * BATCH * NDIM];    // 11.8 MB
__device__ float g_b[INCH * OUTCH];

__device__ __forceinline__ uint32_t smem_to_u32(const void* p) {
    uint32_t a;
    asm("{ .reg .u64 t; cvta.to.shared.u64 t, %1; cvt.u32.u64 %0, t; }"
        : "=r"(a) : "l"(p));
    return a;
}
__device__ __forceinline__ void split_bf16(float x, __nv_bfloat16& h, __nv_bfloat16& l) {
    h = __float2bfloat16(x);
    l = __float2bfloat16(x - __bfloat162float(h));
}
__device__ __forceinline__ void ldsm4(uint32_t& r0, uint32_t& r1, uint32_t& r2,
                                      uint32_t& r3, uint32_t addr) {
    asm volatile("ldmatrix.sync.aligned.m8n8.x4.shared.b16 {%0,%1,%2,%3}, [%4];"
                 : "=r"(r0), "=r"(r1), "=r"(r2), "=r"(r3) : "r"(addr));
}
__device__ __forceinline__ void mma16816(float* d, const uint32_t* a,
                                         const uint32_t* b) {
    asm volatile(
        "mma.sync.aligned.m16n8k16.row.col.f32.bf16.bf16.f32 "
        "{%0,%1,%2,%3}, {%4,%5,%6,%7}, {%8,%9}, {%0,%1,%2,%3};"
        : "+f"(d[0]), "+f"(d[1]), "+f"(d[2]), "+f"(d[3])
        : "r"(a[0]), "r"(a[1]), "r"(a[2]), "r"(a[3]), "r"(b[0]), "r"(b[1]));
}
__device__ __forceinline__ void cp16(uint32_t dst, const void* src) {
    asm volatile("cp.async.cg.shared.global [%0], [%1], 16;"
                 :: "r"(dst), "l"(src));
}
__device__ __forceinline__ void cp_commit() {
    asm volatile("cp.async.commit_group;");
}
template <int N>
__device__ __forceinline__ void cp_wait() {
    asm volatile("cp.async.wait_group %0;" :: "n"(N));
}

// ---------------------------------------------------------------------------
// One-time: inp fp32 -> bf16 hi/lo, plus transposed copies.
// ---------------------------------------------------------------------------
__global__ void conv_inp(const float* __restrict__ inp) {
    __shared__ __nv_bfloat16 sh_hi[32][33];
    __shared__ __nv_bfloat16 sh_lo[32][33];
    int ik0 = blockIdx.x * 32, b0 = blockIdx.y * 32;
    int tx = threadIdx.x, ty = threadIdx.y;
    #pragma unroll
    for (int j = 0; j < 4; j++) {
        int bl = ty + 8 * j;
        float x = inp[(size_t)(b0 + bl) * KDIM + ik0 + tx];
        __nv_bfloat16 h, l;
        split_bf16(x, h, l);
        g_inp_hi[(size_t)(b0 + bl) * KDIM + ik0 + tx] = h;
        g_inp_lo[(size_t)(b0 + bl) * KDIM + ik0 + tx] = l;
        sh_hi[tx][bl] = h;
        sh_lo[tx][bl] = l;
    }
    __syncthreads();
    #pragma unroll
    for (int j = 0; j < 4; j++) {
        int ikl = ty + 8 * j;
        g_inpT_hi[(size_t)(ik0 + ikl) * BATCH + b0 + tx] = sh_hi[ikl][tx];
        g_inpT_lo[(size_t)(ik0 + ikl) * BATCH + b0 + tx] = sh_lo[ikl][tx];
    }
}

// ---------------------------------------------------------------------------
// Wc build, chunk-tiled: g_Bt[chunk][ou][64] = c[i,o]*W[i,o,u,k] (bf16 hi/lo).
// One CTA per chunk of 8 capsules. Fully coalesced read and write.
// ---------------------------------------------------------------------------
__global__ void wc_tiled(const float* __restrict__ W, int t) {
    __shared__ float c_s[8][10];
    int chunk = blockIdx.x, i0 = chunk * 8;
    int tid = threadIdx.x;
    if (tid < 8) {
        int i = i0 + tid;
        if (t == 0) {
            #pragma unroll
            for (int o = 0; o < OUTCH; o++) c_s[tid][o] = 0.1f;
        } else {
            float bv[OUTCH], m = -1e30f;
            #pragma unroll
            for (int o = 0; o < OUTCH; o++) {
                bv[o] = g_b[i * OUTCH + o];
                m = fmaxf(m, bv[o]);
            }
            float sum = 0.f;
            #pragma unroll
            for (int o = 0; o < OUTCH; o++) { bv[o] = expf(bv[o] - m); sum += bv[o]; }
            float inv = 1.0f / sum;
            #pragma unroll
            for (int o = 0; o < OUTCH; o++) c_s[tid][o] = bv[o] * inv;
        }
    }
    __syncthreads();
    const float4* W4 = (const float4*)(W + (size_t)i0 * 1280);
    __nv_bfloat16* bh = g_Bt_hi + (size_t)chunk * (NDIM * 64);
    __nv_bfloat16* bl = g_Bt_lo + (size_t)chunk * (NDIM * 64);
    #pragma unroll
    for (int r = 0; r < 10; r++) {
        int q = tid + (r << 8);              // 0..2559 float4s (8 caps x 320)
        int i_off = q / 320;
        int rem = q - i_off * 320;
        int o = rem >> 5;
        int rem2 = rem & 31;
        int u = rem2 >> 1, kh = rem2 & 1;
        float4 f = W4[q];
        float cv = c_s[i_off][o];
        __nv_bfloat16 h0,l0,h1,l1,h2,l2,h3,l3;
        split_bf16(f.x * cv, h0, l0);
        split_bf16(f.y * cv, h1, l1);
        split_bf16(f.z * cv, h2, l2);
        split_bf16(f.w * cv, h3, l3);
        uint2 ph, pl;
        ph.x = (uint32_t)__bfloat16_as_ushort(h0) | ((uint32_t)__bfloat16_as_ushort(h1) << 16);
        ph.y = (uint32_t)__bfloat16_as_ushort(h2) | ((uint32_t)__bfloat16_as_ushort(h3) << 16);
        pl.x = (uint32_t)__bfloat16_as_ushort(l0) | ((uint32_t)__bfloat16_as_ushort(l1) << 16);
        pl.y = (uint32_t)__bfloat16_as_ushort(l2) | ((uint32_t)__bfloat16_as_ushort(l3) << 16);
        int off = (o * 16 + u) * 64 + i_off * 8 + kh * 4;
        *(uint2*)(bh + off) = ph;
        *(uint2*)(bl + off) = pl;
    }
}

// ---------------------------------------------------------------------------
// s-GEMM: grid (2 Mtiles, 72 Ksplits), 256 thr, 8 warps (4M x 2N), tile
// 128x160x128. All operand tiles prefetched via cp.async (2 groups).
// ---------------------------------------------------------------------------
#define PITCH 72   // bf16 smem row pitch (144 B, ldmatrix conflict-free)
#define SGS_AH 0
#define SGS_AL (128*PITCH*2)                 // 18432
#define SGS_BH (2*128*PITCH*2)               // 36864
#define SGS_BL (SGS_BH + 160*PITCH*2)        // 59904
#define SGS_CH (SGS_BL + 160*PITCH*2)        // 82944 bytes per chunk set
#define SGS_TOT (2*SGS_CH)                   // 165888

__global__ void __launch_bounds__(256, 1)
gemm_s(int unused) {
    extern __shared__ char sm[];
    uint32_t sb = smem_to_u32(sm);
    int tid = threadIdx.x, lane = tid & 31, wid = tid >> 5;
    int warp_m = wid & 3, warp_n = wid >> 2;
    int m0 = blockIdx.x * 128;

    // prefetch both chunks
    #pragma unroll
    for (int ch = 0; ch < 2; ch++) {
        int chunk = blockIdx.y * 2 + ch;
        int kb = chunk * 64;
        uint32_t base = sb + ch * SGS_CH;
        #pragma unroll
        for (int r = 0; r < 4; r++) {
            int e = tid + (r << 8);
            int row = e >> 3, j = e & 7;
            uint32_t d = (uint32_t)(row * PITCH + j * 8) * 2;
            const __nv_bfloat16* sa = g_inp_hi + (size_t)(m0 + row) * KDIM + kb + j * 8;
            const __nv_bfloat16* sl = g_inp_lo + (size_t)(m0 + row) * KDIM + kb + j * 8;
            cp16(base + SGS_AH + d, sa);
            cp16(base + SGS_AL + d, sl);
        }
        #pragma unroll
        for (int r = 0; r < 5; r++) {
            int e = tid + (r << 8);
            int row = e >> 3, j = e & 7;
            uint32_t d = (uint32_t)(row * PITCH + j * 8) * 2;
            cp16(base + SGS_BH + d, g_Bt_hi + (size_t)chunk * (NDIM * 64) + e * 8);
            cp16(base + SGS_BL + d, g_Bt_lo + (size_t)chunk * (NDIM * 64) + e * 8);
        }
        cp_commit();
    }

    float acc[2][10][4];
    #pragma unroll
    for (int mi = 0; mi < 2; mi++)
        #pragma unroll
        for (int nt = 0; nt < 10; nt++)
            #pragma unroll
            for (int r = 0; r < 4; r++) acc[mi][nt][r] = 0.f;

    int a_row_l = ((lane >> 3) & 1) * 8 + (lane & 7);
    int a_k_l   = (lane >> 4) * 8;
    int b_dn_l  = ((lane >> 4) & 1) * 8 + (lane & 7);
    int b_dk_l  = ((lane >> 3) & 1) * 8;

    auto do_pass = [&](uint32_t sa, uint32_t sbp) {
        #pragma unroll
        for (int ks = 0; ks < 4; ks++) {
            uint32_t af[2][4], bf[10][2];
            #pragma unroll
            for (int mi = 0; mi < 2; mi++) {
                int row = warp_m * 32 + mi * 16 + a_row_l;
                ldsm4(af[mi][0], af[mi][1], af[mi][2], af[mi][3],
                      sa + (uint32_t)(row * PITCH + ks * 16 + a_k_l) * 2);
            }
            #pragma unroll
            for (int p = 0; p < 5; p++) {
                int row = warp_n * 80 + p * 16 + b_dn_l;
                ldsm4(bf[2*p][0], bf[2*p][1], bf[2*p+1][0], bf[2*p+1][1],
                      sbp + (uint32_t)(row * PITCH + ks * 16 + b_dk_l) * 2);
            }
            #pragma unroll
            for (int mi = 0; mi < 2; mi++)
                #pragma unroll
                for (int nt = 0; nt < 10; nt++)
                    mma16816(acc[mi][nt], af[mi], bf[nt]);
        }
    };

    cp_wait<1>();
    __syncthreads();
    do_pass(sb + SGS_AH, sb + SGS_BH);
    do_pass(sb + SGS_AH, sb + SGS_BL);
    do_pass(sb + SGS_AL, sb + SGS_BH);
    cp_wait<0>();
    __syncthreads();
    do_pass(sb + SGS_CH + SGS_AH, sb + SGS_CH + SGS_BH);
    do_pass(sb + SGS_CH + SGS_AH, sb + SGS_CH + SGS_BL);
    do_pass(sb + SGS_CH + SGS_AL, sb + SGS_CH + SGS_BH);

    float* out = g_part_s + ((size_t)blockIdx.y * 2 + blockIdx.x) * 128 * NDIM;
    int r_l = lane >> 2, c_l = (lane & 3) * 2;
    #pragma unroll
    for (int mi = 0; mi < 2; mi++) {
        int row = warp_m * 32 + mi * 16 + r_l;
        #pragma unroll
        for (int nt = 0; nt < 10; nt++) {
            int col = warp_n * 80 + nt * 8 + c_l;
            *(float2*)(out + (size_t)row * NDIM + col) =
                make_float2(acc[mi][nt][0], acc[mi][nt][1]);
            *(float2*)(out + (size_t)(row + 8) * NDIM + col) =
                make_float2(acc[mi][nt][2], acc[mi][nt][3]);
        }
    }
}

// ---------------------------------------------------------------------------
// Split-K reduce + squash, one thread per output element.
// ---------------------------------------------------------------------------
__global__ void squash_k(float* __restrict__ out, int t) {
    int idx = blockIdx.x * 256 + threadIdx.x;    // b*160 + o*16 + u
    float a0 = 0.f, a1 = 0.f, a2 = 0.f, a3 = 0.f;
    #pragma unroll
    for (int sp = 0; sp < SPLITS_S; sp += 4) {
        a0 += g_part_s[(size_t)(sp + 0) * (BATCH * NDIM) + idx];
        a1 += g_part_s[(size_t)(sp + 1) * (BATCH * NDIM) + idx];
        a2 += g_part_s[(size_t)(sp + 2) * (BATCH * NDIM) + idx];
        a3 += g_part_s[(size_t)(sp + 3) * (BATCH * NDIM) + idx];
    }
    float s = (a0 + a1) + (a2 + a3);
    float sq = s * s;
    sq += __shfl_xor_sync(0xffffffffu, sq, 8);
    sq += __shfl_xor_sync(0xffffffffu, sq, 4);
    sq += __shfl_xor_sync(0xffffffffu, sq, 2);
    sq += __shfl_xor_sync(0xffffffffu, sq, 1);
    float scale = sq / ((1.0f + sq) * sqrtf(sq + 1e-9f));
    float v = s * scale;
    if (t == 2) {
        out[idx] = v;
    } else {
        int b = idx / NDIM;
        int ou = idx - b * NDIM;
        __nv_bfloat16 h, l;
        split_bf16(v, h, l);
        g_vT_hi[(size_t)ou * BATCH + b] = h;
        g_vT_lo[(size_t)ou * BATCH + b] = l;
    }
}

// ---------------------------------------------------------------------------
// M-GEMM (M[ik,ou] = inpT @ vT^T) with fused b-update.
// grid 144 (64 ik rows = 8 capsules per CTA), K=256 over 3 passes x 4 chunks.
// 8 warps (4M x 2N), warp tile 16x80, cp.async 2-stage pipeline.
// ---------------------------------------------------------------------------
#define SGM_AS 0
#define SGM_BS (64*PITCH*2)                  // 9216
#define SGM_STAGE (SGM_BS + 160*PITCH*2)     // 32256 bytes per stage
#define SGM_TOT (2*SGM_STAGE)                // 64512 (>= 40960 epilogue M_s)

__global__ void __launch_bounds__(256, 1)
gemm_m(const float* __restrict__ W, int t) {
    extern __shared__ char sm[];
    uint32_t sb = smem_to_u32(sm);
    int tid = threadIdx.x, lane = tid & 31, wid = tid >> 5;
    int warp_m = wid & 3, warp_n = wid >> 2;
    int m0 = blockIdx.x * 64;

    auto issue = [&](int g) {
        int p = g >> 2, c = g & 3;
        const __nv_bfloat16* Asrc = (p == 2) ? g_inpT_lo : g_inpT_hi;
        const __nv_bfloat16* Bsrc = (p == 1) ? g_vT_lo : g_vT_hi;
        int kb = c << 6;
        uint32_t base = sb + (g & 1) * SGM_STAGE;
        #pragma unroll
        for (int r = 0; r < 2; r++) {
            int e = tid + (r << 8);
            int row = e >> 3, j = e & 7;
            cp16(base + SGM_AS + (uint32_t)(row * PITCH + j * 8) * 2,
                 Asrc + (size_t)(m0 + row) * BATCH + kb + j * 8);
        }
        #pragma unroll
        for (int r = 0; r < 5; r++) {
            int e = tid + (r << 8);
            int row = e >> 3, j = e & 7;
            cp16(base + SGM_BS + (uint32_t)(row * PITCH + j * 8) * 2,
                 Bsrc + (size_t)row * BATCH + kb + j * 8);
        }
        cp_commit();
    };

    float acc[10][4];
    #pragma unroll
    for (int nt = 0; nt < 10; nt++)
        #pragma unroll
        for (int r = 0; r < 4; r++) acc[nt][r] = 0.f;

    int a_row_l = ((lane >> 3) & 1) * 8 + (lane & 7);
    int a_k_l   = (lane >> 4) * 8;
    int b_dn_l  = ((lane >> 4) & 1) * 8 + (lane & 7);
    int b_dk_l  = ((lane >> 3) & 1) * 8;

    issue(0);
    for (int g = 0; g < 12; g++) {
        if (g + 1 < 12) {
            issue(g + 1);
            cp_wait<1>();
        } else {
            cp_wait<0>();
        }
        __syncthreads();
        uint32_t base = sb + (g & 1) * SGM_STAGE;
        #pragma unroll
        for (int ks = 0; ks < 4; ks++) {
            uint32_t af[4], bf[10][2];
            int row = warp_m * 16 + a_row_l;
            ldsm4(af[0], af[1], af[2], af[3],
                  base + SGM_AS + (uint32_t)(row * PITCH + ks * 16 + a_k_l) * 2);
            #pragma unroll
            for (int p = 0; p < 5; p++) {
                int brow = warp_n * 80 + p * 16 + b_dn_l;
                ldsm4(bf[2*p][0], bf[2*p][1], bf[2*p+1][0], bf[2*p+1][1],
                      base + SGM_BS + (uint32_t)(brow * PITCH + ks * 16 + b_dk_l) * 2);
            }
            #pragma unroll
            for (int nt = 0; nt < 10; nt++)
                mma16816(acc[nt], af, bf[nt]);
        }
        __syncthreads();   // stage buffer free before overwrite
    }

    // Stage M tile [64][160] fp32 in smem (reuses pipeline buffers).
    float* M_s = (float*)sm;
    int r_l = lane >> 2, c_l = (lane & 3) * 2;
    int row = warp_m * 16 + r_l;
    #pragma unroll
    for (int nt = 0; nt < 10; nt++) {
        int col = warp_n * 80 + nt * 8 + c_l;
        *(float2*)(M_s + row * NDIM + col) = make_float2(acc[nt][0], acc[nt][1]);
        *(float2*)(M_s + (row + 8) * NDIM + col) = make_float2(acc[nt][2], acc[nt][3]);
    }
    __syncthreads();

    // Fused b-update: delta[i,o] = (1/B) sum_{k,u} W[i,o,u,k]*M[i8+k][o16+u]
    // 80 outputs per CTA (8 capsules x 10), 10 per warp.
    #pragma unroll
    for (int ee = 0; ee < 10; ee++) {
        int e = wid * 10 + ee;
        int i_rel = e / 10, o = e - i_rel * 10;
        int i = blockIdx.x * 8 + i_rel;
        float sum = 0.f;
        #pragma unroll
        for (int j = 0; j < 4; j++) {
            int f = lane + (j << 5);           // 0..127
            int k = f >> 4, u = f & 15;
            sum = fmaf(W[(size_t)i * 1280 + (o << 7) + (u << 3) + k],
                       M_s[(i_rel * 8 + k) * NDIM + o * 16 + u], sum);
        }
        #pragma unroll
        for (int off = 16; off; off >>= 1)
            sum += __shfl_xor_sync(0xffffffffu, sum, off);
        if (lane == 0) {
            float d = sum * (1.0f / (float)BATCH);
            int gw = i * OUTCH + o;
            g_b[gw] = (t == 0) ? d : (g_b[gw] + d);
        }
    }
}

// ---------------------------------------------------------------------------
extern "C" void kernel_launch(void* const* d_in, const int* in_sizes, int n_in,
                              void* d_out, int out_size) {
    const float* inp = (const float*)d_in[0];  // [256,1152,8]
    const float* W   = (const float*)d_in[1];  // [1152,10,16,8]
    float* out = (float*)d_out;                // [256,10,16]

    cudaFuncSetAttribute(gemm_s, cudaFuncAttributeMaxDynamicSharedMemorySize, SGS_TOT);
    cudaFuncSetAttribute(gemm_m, cudaFuncAttributeMaxDynamicSharedMemorySize, SGM_TOT);

    conv_inp<<<dim3(KDIM / 32, BATCH / 32), dim3(32, 8)>>>(inp);

    for (int t = 0; t < 3; t++) {
        wc_tiled<<<NCHUNK, 256>>>(W, t);
        gemm_s<<<dim3(2, SPLITS_S), 256, SGS_TOT>>>(0);
        squash_k<<<BATCH * NDIM / 256, 256>>>(out, t);
        if (t < 2)
            gemm_m<<<KDIM / 64, 256, SGM_TOT>>>(W, t);
    }
}